// round 15
// baseline (speedup 1.0000x reference)
#include <cuda_runtime.h>
#include <cuda_fp16.h>

#define N_NODES 100000
#define DIM 64
#define STRIDE 64               // padded adjacency slots per node
#define PROJ_MAXNORM 0.996f     // (1 - 4e-3)/sqrt(c), c=1
#define MIN_NORM 1e-15f
#define GROWS 128               // rows per gemm tile
#define GBLOCKS 148             // persistent gemm blocks (1 per SM)

// Scratch (device globals — no allocation allowed).
// g_h has ONE EXTRA ROW at index N_NODES: all-zeros (zero-init, never
// written) — additive-identity target for padded gather slots.
// g_cur and g_done are zero-init at load and reset by k_agg every call.
__device__ float        g_h[(N_NODES + 1) * DIM];    // x@W, scaled in-place
__device__ int          g_cur[N_NODES];              // degree counters
__device__ int          g_adjpad[N_NODES * STRIDE];  // padded adjacency
__device__ unsigned int g_done;                      // grid-barrier counter

__device__ __forceinline__ unsigned int h2_as_u32(__half2 h) {
    return *reinterpret_cast<unsigned int*>(&h);
}
__device__ __forceinline__ unsigned int smem_u32(const void* p) {
    return (unsigned int)__cvta_generic_to_shared(p);
}
// packed fp32 pairwise add: a += v (2 fp32 adds in one instruction)
__device__ __forceinline__ void addf32x2(unsigned long long& a,
                                         unsigned long long v) {
    asm("add.rn.f32x2 %0, %0, %1;" : "+l"(a) : "l"(v));
}

// ---------------------------------------------------------------------------
// 1) FUSED: fill (blocks >= GBLOCKS) || gemm (blocks < GBLOCKS), then a
//    software grid barrier (all blocks resident by construction), then a
//    cooperative in-place scale of h by rsqrt(deg+1).
__global__ void __launch_bounds__(256, 3) k_fused(const float* __restrict__ x,
                                                  const float* __restrict__ W,
                                                  const int* __restrict__ src,
                                                  const int* __restrict__ dst,
                                                  int E, int n, int ntiles) {
    __shared__ __half xh[GROWS][72];   // gemm role only
    __shared__ __half WhT[64][72];

    int tid = threadIdx.x;

    if (blockIdx.x >= GBLOCKS) {
        // ---------------- fill role: grid-stride over 8-edge batches -------
        int octs = (E + 7) >> 3;
        int fstride = (gridDim.x - GBLOCKS) * blockDim.x;
        for (int i = (blockIdx.x - GBLOCKS) * blockDim.x + tid; i < octs;
             i += fstride) {
            int e0 = i * 8;
            if (e0 + 7 < E) {
                int4 da = *reinterpret_cast<const int4*>(dst + e0);
                int4 db = *reinterpret_cast<const int4*>(dst + e0 + 4);
                int4 sa = *reinterpret_cast<const int4*>(src + e0);
                int4 sb = *reinterpret_cast<const int4*>(src + e0 + 4);
                int p0 = atomicAdd(&g_cur[da.x], 1);
                int p1 = atomicAdd(&g_cur[da.y], 1);
                int p2 = atomicAdd(&g_cur[da.z], 1);
                int p3 = atomicAdd(&g_cur[da.w], 1);
                int p4 = atomicAdd(&g_cur[db.x], 1);
                int p5 = atomicAdd(&g_cur[db.y], 1);
                int p6 = atomicAdd(&g_cur[db.z], 1);
                int p7 = atomicAdd(&g_cur[db.w], 1);
                if (p0 < STRIDE) g_adjpad[da.x * STRIDE + p0] = sa.x;
                if (p1 < STRIDE) g_adjpad[da.y * STRIDE + p1] = sa.y;
                if (p2 < STRIDE) g_adjpad[da.z * STRIDE + p2] = sa.z;
                if (p3 < STRIDE) g_adjpad[da.w * STRIDE + p3] = sa.w;
                if (p4 < STRIDE) g_adjpad[db.x * STRIDE + p4] = sb.x;
                if (p5 < STRIDE) g_adjpad[db.y * STRIDE + p5] = sb.y;
                if (p6 < STRIDE) g_adjpad[db.z * STRIDE + p6] = sb.z;
                if (p7 < STRIDE) g_adjpad[db.w * STRIDE + p7] = sb.w;
            } else {
                for (int e = e0; e < E; e++) {
                    int d = dst[e];
                    int p = atomicAdd(&g_cur[d], 1);
                    if (p < STRIDE) g_adjpad[d * STRIDE + p] = src[e];
                }
            }
        }
    } else {
        // ---------------- gemm role: HMMA, UNscaled fp32 out ---------------
        int warp = tid >> 5;
        int lane = tid & 31;
        int m0 = warp * 16;

        #pragma unroll
        for (int i = 0; i < 4; i++) {
            int idx = tid + i * 256;
            int k  = idx >> 4;
            int c4 = idx & 15;
            float4 wv = reinterpret_cast<const float4*>(W)[idx];
            WhT[c4 * 4 + 0][k] = __float2half(wv.x);
            WhT[c4 * 4 + 1][k] = __float2half(wv.y);
            WhT[c4 * 4 + 2][k] = __float2half(wv.z);
            WhT[c4 * 4 + 3][k] = __float2half(wv.w);
        }

        for (int tile = blockIdx.x; tile < ntiles; tile += GBLOCKS) {
            int rowBase = tile * GROWS;

            #pragma unroll
            for (int i = 0; i < 8; i++) {
                int idx = tid + i * 256;
                int r  = idx >> 4;
                int c4 = idx & 15;
                int gr = rowBase + r;
                if (gr >= n) gr = n - 1;
                float4 xv = reinterpret_cast<const float4*>(x + (size_t)gr * DIM)[c4];
                __half2 h0 = __floats2half2_rn(xv.x, xv.y);
                __half2 h1 = __floats2half2_rn(xv.z, xv.w);
                *reinterpret_cast<uint2*>(&xh[r][c4 * 4]) =
                    make_uint2(h2_as_u32(h0), h2_as_u32(h1));
            }
            __syncthreads();

            float acc[8][4];
            #pragma unroll
            for (int nt = 0; nt < 8; nt++)
                #pragma unroll
                for (int i = 0; i < 4; i++) acc[nt][i] = 0.f;

            #pragma unroll
            for (int ks = 0; ks < 4; ks++) {
                int k0 = ks * 16;
                int ar = m0 + (lane & 7) + 8 * ((lane >> 3) & 1);
                int ac = k0 + 8 * (lane >> 4);
                unsigned int addrA = smem_u32(&xh[ar][ac]);
                unsigned int a0, a1, a2, a3;
                asm volatile("ldmatrix.sync.aligned.m8n8.x4.shared.b16 {%0,%1,%2,%3}, [%4];"
                             : "=r"(a0), "=r"(a1), "=r"(a2), "=r"(a3) : "r"(addrA));

                #pragma unroll
                for (int nt = 0; nt < 8; nt++) {
                    int br = nt * 8 + (lane & 7);
                    int bc = k0 + 8 * ((lane >> 3) & 1);
                    unsigned int addrB = smem_u32(&WhT[br][bc]);
                    unsigned int b0, b1;
                    asm volatile("ldmatrix.sync.aligned.m8n8.x2.shared.b16 {%0,%1}, [%2];"
                                 : "=r"(b0), "=r"(b1) : "r"(addrB));
                    asm volatile(
                        "mma.sync.aligned.m16n8k16.row.col.f32.f16.f16.f32 "
                        "{%0,%1,%2,%3}, {%4,%5,%6,%7}, {%8,%9}, {%0,%1,%2,%3};"
                        : "+f"(acc[nt][0]), "+f"(acc[nt][1]),
                          "+f"(acc[nt][2]), "+f"(acc[nt][3])
                        : "r"(a0), "r"(a1), "r"(a2), "r"(a3), "r"(b0), "r"(b1));
                }
            }

            int row1 = rowBase + m0 + (lane >> 2);
            int row2 = row1 + 8;
            int colh2 = lane & 3;

            #pragma unroll
            for (int nt = 0; nt < 8; nt++) {
                int c2 = nt * 4 + colh2;
                if (row1 < n) {
                    float2 o = make_float2(acc[nt][0], acc[nt][1]);
                    *reinterpret_cast<float2*>(&g_h[(size_t)row1 * DIM + c2 * 2]) = o;
                }
                if (row2 < n) {
                    float2 o = make_float2(acc[nt][2], acc[nt][3]);
                    *reinterpret_cast<float2*>(&g_h[(size_t)row2 * DIM + c2 * 2]) = o;
                }
            }
            __syncthreads();
        }
    }

    // ---------------- software grid barrier ---------------------------------
    // All gridDim.x blocks are resident simultaneously (grid <= 3 blocks/SM
    // guaranteed by __launch_bounds__(256,3); grid = 148 + ~196 = ~344 <= 444),
    // so every block reaches the arrive and the spin always terminates.
    __syncthreads();
    __threadfence();                      // release my writes
    if (tid == 0) {
        atomicAdd(&g_done, 1u);
        while (atomicAdd(&g_done, 0u) < gridDim.x) __nanosleep(64);
    }
    __syncthreads();
    __threadfence();                      // acquire (flush stale L1)

    // ---------------- cooperative scale: h[row] *= rsqrt(deg+1) -------------
    int total4 = n * 16;                  // float4 chunks (16 per row)
    for (int idx = blockIdx.x * blockDim.x + tid; idx < total4;
         idx += gridDim.x * blockDim.x) {
        int row = idx >> 4;
        float s = rsqrtf((float)(min(g_cur[row], STRIDE) + 1));
        float4* p = reinterpret_cast<float4*>(g_h) + idx;
        float4 v = *p;
        v.x *= s; v.y *= s; v.z *= s; v.w *= s;
        *p = v;
    }
}

// ---------------------------------------------------------------------------
// 2) gather-aggregate + finalize: TWO nodes per warp (identical to R13/R14;
//    additionally resets g_done for the next graph replay).
__global__ void __launch_bounds__(256) k_agg(const float* __restrict__ b,
                                             float* __restrict__ out,
                                             int npairs) {
    if (blockIdx.x == 0 && threadIdx.x == 0) g_done = 0;  // reset barrier

    int w = (blockIdx.x * blockDim.x + threadIdx.x) >> 5;
    if (w >= npairs) return;
    int lane = threadIdx.x & 31;
    int half = lane >> 4;
    int hl = lane & 15;
    int d = w * 2 + half;

    int deg = min(g_cur[d], STRIDE);
    if (hl == 0) g_cur[d] = 0;            // self-clean (sole owner of d)
    const int* adj = &g_adjpad[(size_t)d * STRIDE];
    int srcbase = half << 4;

    int s16 = (hl < deg) ? __ldg(&adj[hl]) : N_NODES;

    unsigned long long a0 = 0ull, a1 = 0ull;
    unsigned long long b0_ = 0ull, b1_ = 0ull;

    #pragma unroll
    for (int j = 0; j < 16; j += 2) {
        int sa = __shfl_sync(0xffffffffu, s16, srcbase + j);
        int sb = __shfl_sync(0xffffffffu, s16, srcbase + j + 1);
        ulonglong2 va = *reinterpret_cast<const ulonglong2*>(
            &g_h[(size_t)sa * DIM + hl * 4]);
        ulonglong2 vb = *reinterpret_cast<const ulonglong2*>(
            &g_h[(size_t)sb * DIM + hl * 4]);
        addf32x2(a0, va.x); addf32x2(a1, va.y);
        addf32x2(b0_, vb.x); addf32x2(b1_, vb.y);
    }

    int odeg = __shfl_xor_sync(0xffffffffu, deg, 16);
    int mdeg = max(deg, odeg);
    for (int base = 16; base < mdeg; base += 16) {
        int e = base + hl;
        int s = (e < deg) ? __ldg(&adj[e]) : N_NODES;
        int cnt = min(16, mdeg - base);
        #pragma unroll 4
        for (int j = 0; j < cnt; j++) {
            int sj = __shfl_sync(0xffffffffu, s, srcbase + j);
            ulonglong2 v = *reinterpret_cast<const ulonglong2*>(
                &g_h[(size_t)sj * DIM + hl * 4]);
            addf32x2(a0, v.x); addf32x2(a1, v.y);
        }
    }

    ulonglong2 vs = *reinterpret_cast<const ulonglong2*>(
        &g_h[(size_t)d * DIM + hl * 4]);
    addf32x2(a0, vs.x); addf32x2(a1, vs.y);
    addf32x2(a0, b0_);  addf32x2(a1, b1_);

    float ax, ay, az, aw;
    {
        unsigned int lo, hi;
        asm("mov.b64 {%0, %1}, %2;" : "=r"(lo), "=r"(hi) : "l"(a0));
        ax = __uint_as_float(lo); ay = __uint_as_float(hi);
        asm("mov.b64 {%0, %1}, %2;" : "=r"(lo), "=r"(hi) : "l"(a1));
        az = __uint_as_float(lo); aw = __uint_as_float(hi);
    }

    float dis = rsqrtf((float)(deg + 1));
    float4 bb = *reinterpret_cast<const float4*>(&b[hl * 4]);
    float4 vv;
    vv.x = fmaf(ax, dis, bb.x);
    vv.y = fmaf(ay, dis, bb.y);
    vv.z = fmaf(az, dis, bb.z);
    vv.w = fmaf(aw, dis, bb.w);

    float ss = vv.x * vv.x + vv.y * vv.y + vv.z * vv.z + vv.w * vv.w;
    ss += __shfl_xor_sync(0xffffffffu, ss, 1);
    ss += __shfl_xor_sync(0xffffffffu, ss, 2);
    ss += __shfl_xor_sync(0xffffffffu, ss, 4);
    ss += __shfl_xor_sync(0xffffffffu, ss, 8);

    float norm = sqrtf(ss);
    float un = fmaxf(norm, MIN_NORM);
    float t = tanhf(un);
    float scale = fminf(t, PROJ_MAXNORM) / un;

    float4 o = make_float4(vv.x * scale, vv.y * scale, vv.z * scale, vv.w * scale);
    *reinterpret_cast<float4*>(&out[(size_t)d * DIM + hl * 4]) = o;
}

// ---------------------------------------------------------------------------
extern "C" void kernel_launch(void* const* d_in, const int* in_sizes, int n_in,
                              void* d_out, int out_size) {
    const float* x  = (const float*)d_in[0];   // [N, 64]
    const float* W  = (const float*)d_in[1];   // [64, 64]
    const float* b  = (const float*)d_in[2];   // [64]
    const int*   ei = (const int*)d_in[3];     // [2, E]
    float* out = (float*)d_out;                // [N, 64]

    int E = in_sizes[3] / 2;
    const int* src = ei;
    const int* dst = ei + E;

    // 1) fused: fill || gemm, grid barrier, cooperative scale.
    //    fill blocks sized so total grid <= 3 blocks/SM residency (<= 444).
    int ntiles = (N_NODES + GROWS - 1) / GROWS;
    int octs = (E + 7) / 8;
    int fillBlocks = (octs + 3 * 256 - 1) / (3 * 256);   // ~3 octs per thread
    if (fillBlocks > 444 - GBLOCKS) fillBlocks = 444 - GBLOCKS;
    k_fused<<<GBLOCKS + fillBlocks, 256>>>(x, W, src, dst, E, N_NODES, ntiles);

    // 2) gather-aggregate + expmap0 + proj (+ barrier reset)
    int npairs = N_NODES / 2;
    k_agg<<<(npairs * 32 + 255) / 256, 256>>>(b, out, npairs);
}

// round 16
// speedup vs baseline: 1.5133x; 1.5133x over previous
#include <cuda_runtime.h>
#include <cuda_fp16.h>

#define N_NODES 100000
#define DIM 64
#define STRIDE 64               // padded adjacency slots per node
#define PROJ_MAXNORM 0.996f     // (1 - 4e-3)/sqrt(c), c=1
#define MIN_NORM 1e-15f
#define GROWS 128               // rows per gemm tile
#define GBLOCKS 296             // persistent gemm blocks (2 per SM)

// Scratch (device globals — no allocation allowed).
// g_h extra row at N_NODES: all-zeros (never written) — gather identity.
// g_cur / g_fill_done zero-init at load, reset by k_agg each call.
__device__ float        g_h[(N_NODES + 1) * DIM];    // x@W, scaled in-place
__device__ int          g_cur[N_NODES];              // degree counters
__device__ int          g_adjpad[N_NODES * STRIDE];  // padded adjacency
__device__ unsigned int g_fill_done;                 // fill-completion counter

__device__ __forceinline__ unsigned int h2_as_u32(__half2 h) {
    return *reinterpret_cast<unsigned int*>(&h);
}
__device__ __forceinline__ unsigned int smem_u32(const void* p) {
    return (unsigned int)__cvta_generic_to_shared(p);
}
// packed fp32 pairwise add: a += v (2 fp32 adds in one instruction)
__device__ __forceinline__ void addf32x2(unsigned long long& a,
                                         unsigned long long v) {
    asm("add.rn.f32x2 %0, %0, %1;" : "+l"(a) : "l"(v));
}

// ---------------------------------------------------------------------------
// 1) FUSED: fill (blocks >= GBLOCKS; R14 config: one 8-edge oct per thread,
//    exit immediately) || gemm (blocks < GBLOCKS; unscaled HMMA). Gemm blocks
//    then poll the fill-done flag (one-way wait; fill never waits) and scale
//    their own tiles by rsqrt(deg+1) in place.
__global__ void __launch_bounds__(256, 4) k_fused(const float* __restrict__ x,
                                                  const float* __restrict__ W,
                                                  const int* __restrict__ src,
                                                  const int* __restrict__ dst,
                                                  int E, int n, int ntiles,
                                                  int fillBlocks) {
    __shared__ __half xh[GROWS][72];   // gemm role only
    __shared__ __half WhT[64][72];

    int tid = threadIdx.x;

    if (blockIdx.x >= GBLOCKS) {
        // ---------------- fill role (R14-identical work shape) -------------
        int i = (blockIdx.x - GBLOCKS) * blockDim.x + tid;  // oct index
        int e0 = i * 8;
        if (e0 + 7 < E) {
            int4 da = *reinterpret_cast<const int4*>(dst + e0);
            int4 db = *reinterpret_cast<const int4*>(dst + e0 + 4);
            int4 sa = *reinterpret_cast<const int4*>(src + e0);
            int4 sb = *reinterpret_cast<const int4*>(src + e0 + 4);
            int p0 = atomicAdd(&g_cur[da.x], 1);
            int p1 = atomicAdd(&g_cur[da.y], 1);
            int p2 = atomicAdd(&g_cur[da.z], 1);
            int p3 = atomicAdd(&g_cur[da.w], 1);
            int p4 = atomicAdd(&g_cur[db.x], 1);
            int p5 = atomicAdd(&g_cur[db.y], 1);
            int p6 = atomicAdd(&g_cur[db.z], 1);
            int p7 = atomicAdd(&g_cur[db.w], 1);
            if (p0 < STRIDE) g_adjpad[da.x * STRIDE + p0] = sa.x;
            if (p1 < STRIDE) g_adjpad[da.y * STRIDE + p1] = sa.y;
            if (p2 < STRIDE) g_adjpad[da.z * STRIDE + p2] = sa.z;
            if (p3 < STRIDE) g_adjpad[da.w * STRIDE + p3] = sa.w;
            if (p4 < STRIDE) g_adjpad[db.x * STRIDE + p4] = sb.x;
            if (p5 < STRIDE) g_adjpad[db.y * STRIDE + p5] = sb.y;
            if (p6 < STRIDE) g_adjpad[db.z * STRIDE + p6] = sb.z;
            if (p7 < STRIDE) g_adjpad[db.w * STRIDE + p7] = sb.w;
        } else if (e0 < E) {
            for (int e = e0; e < E; e++) {
                int d = dst[e];
                int p = atomicAdd(&g_cur[d], 1);
                if (p < STRIDE) g_adjpad[d * STRIDE + p] = src[e];
            }
        }
        // arrive: release my writes, one count per block
        __threadfence();
        __syncthreads();
        if (tid == 0) atomicAdd(&g_fill_done, 1u);
        return;
    }

    // ---------------- gemm role: HMMA, UNscaled fp32 out -------------------
    int warp = tid >> 5;
    int lane = tid & 31;
    int m0 = warp * 16;

    #pragma unroll
    for (int i = 0; i < 4; i++) {
        int idx = tid + i * 256;
        int k  = idx >> 4;
        int c4 = idx & 15;
        float4 wv = reinterpret_cast<const float4*>(W)[idx];
        WhT[c4 * 4 + 0][k] = __float2half(wv.x);
        WhT[c4 * 4 + 1][k] = __float2half(wv.y);
        WhT[c4 * 4 + 2][k] = __float2half(wv.z);
        WhT[c4 * 4 + 3][k] = __float2half(wv.w);
    }

    for (int tile = blockIdx.x; tile < ntiles; tile += GBLOCKS) {
        int rowBase = tile * GROWS;

        #pragma unroll
        for (int i = 0; i < 8; i++) {
            int idx = tid + i * 256;
            int r  = idx >> 4;
            int c4 = idx & 15;
            int gr = rowBase + r;
            if (gr >= n) gr = n - 1;
            float4 xv = reinterpret_cast<const float4*>(x + (size_t)gr * DIM)[c4];
            __half2 h0 = __floats2half2_rn(xv.x, xv.y);
            __half2 h1 = __floats2half2_rn(xv.z, xv.w);
            *reinterpret_cast<uint2*>(&xh[r][c4 * 4]) =
                make_uint2(h2_as_u32(h0), h2_as_u32(h1));
        }
        __syncthreads();

        float acc[8][4];
        #pragma unroll
        for (int nt = 0; nt < 8; nt++)
            #pragma unroll
            for (int i = 0; i < 4; i++) acc[nt][i] = 0.f;

        #pragma unroll
        for (int ks = 0; ks < 4; ks++) {
            int k0 = ks * 16;
            int ar = m0 + (lane & 7) + 8 * ((lane >> 3) & 1);
            int ac = k0 + 8 * (lane >> 4);
            unsigned int addrA = smem_u32(&xh[ar][ac]);
            unsigned int a0, a1, a2, a3;
            asm volatile("ldmatrix.sync.aligned.m8n8.x4.shared.b16 {%0,%1,%2,%3}, [%4];"
                         : "=r"(a0), "=r"(a1), "=r"(a2), "=r"(a3) : "r"(addrA));

            #pragma unroll
            for (int nt = 0; nt < 8; nt++) {
                int br = nt * 8 + (lane & 7);
                int bc = k0 + 8 * ((lane >> 3) & 1);
                unsigned int addrB = smem_u32(&WhT[br][bc]);
                unsigned int b0, b1;
                asm volatile("ldmatrix.sync.aligned.m8n8.x2.shared.b16 {%0,%1}, [%2];"
                             : "=r"(b0), "=r"(b1) : "r"(addrB));
                asm volatile(
                    "mma.sync.aligned.m16n8k16.row.col.f32.f16.f16.f32 "
                    "{%0,%1,%2,%3}, {%4,%5,%6,%7}, {%8,%9}, {%0,%1,%2,%3};"
                    : "+f"(acc[nt][0]), "+f"(acc[nt][1]),
                      "+f"(acc[nt][2]), "+f"(acc[nt][3])
                    : "r"(a0), "r"(a1), "r"(a2), "r"(a3), "r"(b0), "r"(b1));
            }
        }

        int row1 = rowBase + m0 + (lane >> 2);
        int row2 = row1 + 8;
        int colh2 = lane & 3;

        #pragma unroll
        for (int nt = 0; nt < 8; nt++) {
            int c2 = nt * 4 + colh2;
            if (row1 < n) {
                float2 o = make_float2(acc[nt][0], acc[nt][1]);
                *reinterpret_cast<float2*>(&g_h[(size_t)row1 * DIM + c2 * 2]) = o;
            }
            if (row2 < n) {
                float2 o = make_float2(acc[nt][2], acc[nt][3]);
                *reinterpret_cast<float2*>(&g_h[(size_t)row2 * DIM + c2 * 2]) = o;
            }
        }
        __syncthreads();
    }

    // ---- one-way wait for fill completion (fill blocks never wait) --------
    __syncthreads();
    if (tid == 0) {
        volatile unsigned int* f = &g_fill_done;
        while (*f < (unsigned int)fillBlocks) __nanosleep(200);
    }
    __syncthreads();
    __threadfence();   // acquire ordering + L1 coherence before g_cur reads

    // ---- scale own tiles: h[row] *= rsqrt(deg+1) (coalesced) --------------
    for (int tile = blockIdx.x; tile < ntiles; tile += GBLOCKS) {
        int rowBase = tile * GROWS;
        for (int i = tid; i < GROWS * 16; i += 256) {
            int r = rowBase + (i >> 4);
            if (r < n) {
                float s = rsqrtf((float)(min(g_cur[r], STRIDE) + 1));
                float4* p = reinterpret_cast<float4*>(&g_h[(size_t)r * DIM])
                            + (i & 15);
                float4 v = *p;
                v.x *= s; v.y *= s; v.z *= s; v.w *= s;
                *p = v;
            }
        }
    }
}

// ---------------------------------------------------------------------------
// 2) gather-aggregate + finalize: TWO nodes per warp (identical to R13/R14;
//    also resets g_fill_done for the next graph replay).
__global__ void __launch_bounds__(256) k_agg(const float* __restrict__ b,
                                             float* __restrict__ out,
                                             int npairs) {
    if (blockIdx.x == 0 && threadIdx.x == 0) g_fill_done = 0;

    int w = (blockIdx.x * blockDim.x + threadIdx.x) >> 5;
    if (w >= npairs) return;
    int lane = threadIdx.x & 31;
    int half = lane >> 4;
    int hl = lane & 15;
    int d = w * 2 + half;

    int deg = min(g_cur[d], STRIDE);
    if (hl == 0) g_cur[d] = 0;            // self-clean (sole owner of d)
    const int* adj = &g_adjpad[(size_t)d * STRIDE];
    int srcbase = half << 4;

    int s16 = (hl < deg) ? __ldg(&adj[hl]) : N_NODES;

    unsigned long long a0 = 0ull, a1 = 0ull;
    unsigned long long b0_ = 0ull, b1_ = 0ull;

    #pragma unroll
    for (int j = 0; j < 16; j += 2) {
        int sa = __shfl_sync(0xffffffffu, s16, srcbase + j);
        int sb = __shfl_sync(0xffffffffu, s16, srcbase + j + 1);
        ulonglong2 va = *reinterpret_cast<const ulonglong2*>(
            &g_h[(size_t)sa * DIM + hl * 4]);
        ulonglong2 vb = *reinterpret_cast<const ulonglong2*>(
            &g_h[(size_t)sb * DIM + hl * 4]);
        addf32x2(a0, va.x); addf32x2(a1, va.y);
        addf32x2(b0_, vb.x); addf32x2(b1_, vb.y);
    }

    int odeg = __shfl_xor_sync(0xffffffffu, deg, 16);
    int mdeg = max(deg, odeg);
    for (int base = 16; base < mdeg; base += 16) {
        int e = base + hl;
        int s = (e < deg) ? __ldg(&adj[e]) : N_NODES;
        int cnt = min(16, mdeg - base);
        #pragma unroll 4
        for (int j = 0; j < cnt; j++) {
            int sj = __shfl_sync(0xffffffffu, s, srcbase + j);
            ulonglong2 v = *reinterpret_cast<const ulonglong2*>(
                &g_h[(size_t)sj * DIM + hl * 4]);
            addf32x2(a0, v.x); addf32x2(a1, v.y);
        }
    }

    ulonglong2 vs = *reinterpret_cast<const ulonglong2*>(
        &g_h[(size_t)d * DIM + hl * 4]);
    addf32x2(a0, vs.x); addf32x2(a1, vs.y);
    addf32x2(a0, b0_);  addf32x2(a1, b1_);

    float ax, ay, az, aw;
    {
        unsigned int lo, hi;
        asm("mov.b64 {%0, %1}, %2;" : "=r"(lo), "=r"(hi) : "l"(a0));
        ax = __uint_as_float(lo); ay = __uint_as_float(hi);
        asm("mov.b64 {%0, %1}, %2;" : "=r"(lo), "=r"(hi) : "l"(a1));
        az = __uint_as_float(lo); aw = __uint_as_float(hi);
    }

    float dis = rsqrtf((float)(deg + 1));
    float4 bb = *reinterpret_cast<const float4*>(&b[hl * 4]);
    float4 vv;
    vv.x = fmaf(ax, dis, bb.x);
    vv.y = fmaf(ay, dis, bb.y);
    vv.z = fmaf(az, dis, bb.z);
    vv.w = fmaf(aw, dis, bb.w);

    float ss = vv.x * vv.x + vv.y * vv.y + vv.z * vv.z + vv.w * vv.w;
    ss += __shfl_xor_sync(0xffffffffu, ss, 1);
    ss += __shfl_xor_sync(0xffffffffu, ss, 2);
    ss += __shfl_xor_sync(0xffffffffu, ss, 4);
    ss += __shfl_xor_sync(0xffffffffu, ss, 8);

    float norm = sqrtf(ss);
    float un = fmaxf(norm, MIN_NORM);
    float t = tanhf(un);
    float scale = fminf(t, PROJ_MAXNORM) / un;

    float4 o = make_float4(vv.x * scale, vv.y * scale, vv.z * scale, vv.w * scale);
    *reinterpret_cast<float4*>(&out[(size_t)d * DIM + hl * 4]) = o;
}

// ---------------------------------------------------------------------------
extern "C" void kernel_launch(void* const* d_in, const int* in_sizes, int n_in,
                              void* d_out, int out_size) {
    const float* x  = (const float*)d_in[0];   // [N, 64]
    const float* W  = (const float*)d_in[1];   // [64, 64]
    const float* b  = (const float*)d_in[2];   // [64]
    const int*   ei = (const int*)d_in[3];     // [2, E]
    float* out = (float*)d_out;                // [N, 64]

    int E = in_sizes[3] / 2;
    const int* src = ei;
    const int* dst = ei + E;

    // 1) fused: fill || gemm; gemm waits on fill flag, then scales own tiles
    int ntiles = (N_NODES + GROWS - 1) / GROWS;
    int octs = (E + 7) / 8;
    int fillBlocks = (octs + 255) / 256;       // one oct per thread (R14 regime)
    k_fused<<<GBLOCKS + fillBlocks, 256>>>(x, W, src, dst, E, N_NODES, ntiles,
                                           fillBlocks);

    // 2) gather-aggregate + expmap0 + proj (+ flag reset)
    int npairs = N_NODES / 2;
    k_agg<<<(npairs * 32 + 255) / 256, 256>>>(b, out, npairs);
}

// round 17
// speedup vs baseline: 1.6679x; 1.1022x over previous
#include <cuda_runtime.h>
#include <cuda_fp16.h>

#define N_NODES 100000
#define DIM 64
#define STRIDE 64               // padded adjacency slots per node
#define PROJ_MAXNORM 0.996f     // (1 - 4e-3)/sqrt(c), c=1
#define MIN_NORM 1e-15f
#define GROWS 128               // rows per gemm tile
#define GBLOCKS 296             // persistent gemm blocks (2 per SM)

// Scratch (device globals — no allocation allowed).
// g_h extra row at N_NODES: all-zeros (never written) — gather identity.
// g_cur zero-init at load and re-zeroed by k_agg every call.
__device__ float g_h[(N_NODES + 1) * DIM];    // h = x@W (unscaled until k_scale)
__device__ int   g_cur[N_NODES];              // fill cursor == degree after fill
__device__ int   g_adjpad[N_NODES * STRIDE];  // padded adjacency (src ids per dst)

__device__ __forceinline__ unsigned int h2_as_u32(__half2 h) {
    return *reinterpret_cast<unsigned int*>(&h);
}
__device__ __forceinline__ unsigned int smem_u32(const void* p) {
    return (unsigned int)__cvta_generic_to_shared(p);
}
// packed fp32 pairwise add: a += v (2 fp32 adds in one instruction)
__device__ __forceinline__ void addf32x2(unsigned long long& a,
                                         unsigned long long v) {
    asm("add.rn.f32x2 %0, %0, %1;" : "+l"(a) : "l"(v));
}

// ---------------------------------------------------------------------------
// 1) FUSED: blocks [0, GBLOCKS) run the HMMA gemm (UNscaled h out);
//    blocks [GBLOCKS, ...) run adjacency fill (8 edges/thread).
//    The two roles touch disjoint state -> safe concurrency.
__global__ void __launch_bounds__(256) k_fused(const float* __restrict__ x,
                                               const float* __restrict__ W,
                                               const int* __restrict__ src,
                                               const int* __restrict__ dst,
                                               int E, int n, int ntiles) {
    // ---------------- fill role ----------------
    if (blockIdx.x >= GBLOCKS) {
        int i = (blockIdx.x - GBLOCKS) * blockDim.x + threadIdx.x;  // oct index
        int e0 = i * 8;
        if (e0 + 7 < E) {
            int4 da = *reinterpret_cast<const int4*>(dst + e0);
            int4 db = *reinterpret_cast<const int4*>(dst + e0 + 4);
            int4 sa = *reinterpret_cast<const int4*>(src + e0);
            int4 sb = *reinterpret_cast<const int4*>(src + e0 + 4);
            int p0 = atomicAdd(&g_cur[da.x], 1);
            int p1 = atomicAdd(&g_cur[da.y], 1);
            int p2 = atomicAdd(&g_cur[da.z], 1);
            int p3 = atomicAdd(&g_cur[da.w], 1);
            int p4 = atomicAdd(&g_cur[db.x], 1);
            int p5 = atomicAdd(&g_cur[db.y], 1);
            int p6 = atomicAdd(&g_cur[db.z], 1);
            int p7 = atomicAdd(&g_cur[db.w], 1);
            if (p0 < STRIDE) g_adjpad[da.x * STRIDE + p0] = sa.x;
            if (p1 < STRIDE) g_adjpad[da.y * STRIDE + p1] = sa.y;
            if (p2 < STRIDE) g_adjpad[da.z * STRIDE + p2] = sa.z;
            if (p3 < STRIDE) g_adjpad[da.w * STRIDE + p3] = sa.w;
            if (p4 < STRIDE) g_adjpad[db.x * STRIDE + p4] = sb.x;
            if (p5 < STRIDE) g_adjpad[db.y * STRIDE + p5] = sb.y;
            if (p6 < STRIDE) g_adjpad[db.z * STRIDE + p6] = sb.z;
            if (p7 < STRIDE) g_adjpad[db.w * STRIDE + p7] = sb.w;
        } else {
            for (int e = e0; e < E; e++) {
                int d = dst[e];
                int p = atomicAdd(&g_cur[d], 1);
                if (p < STRIDE) g_adjpad[d * STRIDE + p] = src[e];
            }
        }
        return;
    }

    // ---------------- gemm role ----------------
    __shared__ __half xh[GROWS][72];   // x tile, fp16 (pad: conflict-free)
    __shared__ __half WhT[64][72];     // W transposed: WhT[n][k]

    int tid = threadIdx.x;
    int warp = tid >> 5;
    int lane = tid & 31;
    int m0 = warp * 16;                // 16 rows per warp

    // load W transposed once per block (64x64 = 1024 float4)
    #pragma unroll
    for (int i = 0; i < 4; i++) {
        int idx = tid + i * 256;       // float4 index
        int k  = idx >> 4;             // W row (input dim)
        int c4 = idx & 15;             // float4 col group
        float4 wv = reinterpret_cast<const float4*>(W)[idx];
        WhT[c4 * 4 + 0][k] = __float2half(wv.x);
        WhT[c4 * 4 + 1][k] = __float2half(wv.y);
        WhT[c4 * 4 + 2][k] = __float2half(wv.z);
        WhT[c4 * 4 + 3][k] = __float2half(wv.w);
    }

    for (int tile = blockIdx.x; tile < ntiles; tile += GBLOCKS) {
        int rowBase = tile * GROWS;

        #pragma unroll
        for (int i = 0; i < 8; i++) {
            int idx = tid + i * 256;
            int r  = idx >> 4;
            int c4 = idx & 15;
            int gr = rowBase + r;
            if (gr >= n) gr = n - 1;   // clamp (stores guarded in epilogue)
            float4 xv = reinterpret_cast<const float4*>(x + (size_t)gr * DIM)[c4];
            __half2 h0 = __floats2half2_rn(xv.x, xv.y);
            __half2 h1 = __floats2half2_rn(xv.z, xv.w);
            *reinterpret_cast<uint2*>(&xh[r][c4 * 4]) =
                make_uint2(h2_as_u32(h0), h2_as_u32(h1));
        }
        __syncthreads();

        float acc[8][4];
        #pragma unroll
        for (int nt = 0; nt < 8; nt++)
            #pragma unroll
            for (int i = 0; i < 4; i++) acc[nt][i] = 0.f;

        #pragma unroll
        for (int ks = 0; ks < 4; ks++) {
            int k0 = ks * 16;

            int ar = m0 + (lane & 7) + 8 * ((lane >> 3) & 1);
            int ac = k0 + 8 * (lane >> 4);
            unsigned int addrA = smem_u32(&xh[ar][ac]);
            unsigned int a0, a1, a2, a3;
            asm volatile("ldmatrix.sync.aligned.m8n8.x4.shared.b16 {%0,%1,%2,%3}, [%4];"
                         : "=r"(a0), "=r"(a1), "=r"(a2), "=r"(a3) : "r"(addrA));

            #pragma unroll
            for (int nt = 0; nt < 8; nt++) {
                int br = nt * 8 + (lane & 7);
                int bc = k0 + 8 * ((lane >> 3) & 1);
                unsigned int addrB = smem_u32(&WhT[br][bc]);
                unsigned int b0, b1;
                asm volatile("ldmatrix.sync.aligned.m8n8.x2.shared.b16 {%0,%1}, [%2];"
                             : "=r"(b0), "=r"(b1) : "r"(addrB));
                asm volatile(
                    "mma.sync.aligned.m16n8k16.row.col.f32.f16.f16.f32 "
                    "{%0,%1,%2,%3}, {%4,%5,%6,%7}, {%8,%9}, {%0,%1,%2,%3};"
                    : "+f"(acc[nt][0]), "+f"(acc[nt][1]),
                      "+f"(acc[nt][2]), "+f"(acc[nt][3])
                    : "r"(a0), "r"(a1), "r"(a2), "r"(a3), "r"(b0), "r"(b1));
            }
        }

        // epilogue: store UNSCALED fp32 (k_scale applies dis afterwards)
        int row1 = rowBase + m0 + (lane >> 2);   // rows lane/4 and lane/4 + 8
        int row2 = row1 + 8;
        int colh2 = lane & 3;                    // float2 index within n-tile

        #pragma unroll
        for (int nt = 0; nt < 8; nt++) {
            int c2 = nt * 4 + colh2;             // float2 col index (0..31)
            if (row1 < n) {
                float2 o = make_float2(acc[nt][0], acc[nt][1]);
                *reinterpret_cast<float2*>(&g_h[(size_t)row1 * DIM + c2 * 2]) = o;
            }
            if (row2 < n) {
                float2 o = make_float2(acc[nt][2], acc[nt][3]);
                *reinterpret_cast<float2*>(&g_h[(size_t)row2 * DIM + c2 * 2]) = o;
            }
        }
        __syncthreads();   // xh reads complete before next tile overwrites
    }
}

// ---------------------------------------------------------------------------
// 2) scale: h[row] *= rsqrt(deg[row]+1)   (after fill AND gemm complete)
__global__ void k_scale(int n) {
    int idx = blockIdx.x * blockDim.x + threadIdx.x;  // float4 chunk id
    if (idx >= n * 16) return;
    int row = idx >> 4;
    float s = rsqrtf((float)(min(g_cur[row], STRIDE) + 1));
    float4* p = reinterpret_cast<float4*>(g_h) + idx;
    float4 v = *p;
    v.x *= s; v.y *= s; v.z *= s; v.w *= s;
    *p = v;
}

// ---------------------------------------------------------------------------
// 3) gather-aggregate + finalize: TWO nodes per warp (R13/R14 body,
//    blockDim-agnostic). Launched with 64-thread blocks for finer
//    retirement granularity (straggler smoothing).
__global__ void __launch_bounds__(256) k_agg(const float* __restrict__ b,
                                             float* __restrict__ out,
                                             int npairs) {
    int w = (blockIdx.x * blockDim.x + threadIdx.x) >> 5;
    if (w >= npairs) return;
    int lane = threadIdx.x & 31;
    int half = lane >> 4;           // 0 or 1: which node of the pair
    int hl = lane & 15;             // lane within half; covers cols hl*4..hl*4+3
    int d = w * 2 + half;           // N_NODES is even -> always < N_NODES

    int deg = min(g_cur[d], STRIDE);
    if (hl == 0) g_cur[d] = 0;      // self-clean (sole owner of d)
    const int* adj = &g_adjpad[(size_t)d * STRIDE];
    int srcbase = half << 4;        // broadcast source lanes for this half

    // slot indices 0..15 (zero row when slot >= deg)
    int s16 = (hl < deg) ? __ldg(&adj[hl]) : N_NODES;

    unsigned long long a0 = 0ull, a1 = 0ull;   // even-slot accumulator (4 cols)
    unsigned long long b0_ = 0ull, b1_ = 0ull; // odd-slot accumulator

    // fixed 16-slot gather, fully unrolled -> 16 independent LDG.128
    #pragma unroll
    for (int j = 0; j < 16; j += 2) {
        int sa = __shfl_sync(0xffffffffu, s16, srcbase + j);
        int sb = __shfl_sync(0xffffffffu, s16, srcbase + j + 1);
        ulonglong2 va = *reinterpret_cast<const ulonglong2*>(
            &g_h[(size_t)sa * DIM + hl * 4]);
        ulonglong2 vb = *reinterpret_cast<const ulonglong2*>(
            &g_h[(size_t)sb * DIM + hl * 4]);
        addf32x2(a0, va.x); addf32x2(a1, va.y);
        addf32x2(b0_, vb.x); addf32x2(b1_, vb.y);
    }

    // rare tail: slots 16..deg-1
    int odeg = __shfl_xor_sync(0xffffffffu, deg, 16);
    int mdeg = max(deg, odeg);
    for (int base = 16; base < mdeg; base += 16) {
        int e = base + hl;
        int s = (e < deg) ? __ldg(&adj[e]) : N_NODES;
        int cnt = min(16, mdeg - base);
        #pragma unroll 4
        for (int j = 0; j < cnt; j++) {
            int sj = __shfl_sync(0xffffffffu, s, srcbase + j);
            ulonglong2 v = *reinterpret_cast<const ulonglong2*>(
                &g_h[(size_t)sj * DIM + hl * 4]);
            addf32x2(a0, v.x); addf32x2(a1, v.y);
        }
    }

    // self term + merge accumulators
    ulonglong2 vs = *reinterpret_cast<const ulonglong2*>(
        &g_h[(size_t)d * DIM + hl * 4]);
    addf32x2(a0, vs.x); addf32x2(a1, vs.y);
    addf32x2(a0, b0_);  addf32x2(a1, b1_);

    float ax, ay, az, aw;
    {
        unsigned int lo, hi;
        asm("mov.b64 {%0, %1}, %2;" : "=r"(lo), "=r"(hi) : "l"(a0));
        ax = __uint_as_float(lo); ay = __uint_as_float(hi);
        asm("mov.b64 {%0, %1}, %2;" : "=r"(lo), "=r"(hi) : "l"(a1));
        az = __uint_as_float(lo); aw = __uint_as_float(hi);
    }

    float dis = rsqrtf((float)(deg + 1));
    float4 bb = *reinterpret_cast<const float4*>(&b[hl * 4]);
    float4 vv;
    vv.x = fmaf(ax, dis, bb.x);
    vv.y = fmaf(ay, dis, bb.y);
    vv.z = fmaf(az, dis, bb.z);
    vv.w = fmaf(aw, dis, bb.w);

    float ss = vv.x * vv.x + vv.y * vv.y + vv.z * vv.z + vv.w * vv.w;
    ss += __shfl_xor_sync(0xffffffffu, ss, 1);
    ss += __shfl_xor_sync(0xffffffffu, ss, 2);
    ss += __shfl_xor_sync(0xffffffffu, ss, 4);
    ss += __shfl_xor_sync(0xffffffffu, ss, 8);

    float norm = sqrtf(ss);
    float un = fmaxf(norm, MIN_NORM);
    float t = tanhf(un);
    float scale = fminf(t, PROJ_MAXNORM) / un;

    float4 o = make_float4(vv.x * scale, vv.y * scale, vv.z * scale, vv.w * scale);
    *reinterpret_cast<float4*>(&out[(size_t)d * DIM + hl * 4]) = o;
}

// ---------------------------------------------------------------------------
extern "C" void kernel_launch(void* const* d_in, const int* in_sizes, int n_in,
                              void* d_out, int out_size) {
    const float* x  = (const float*)d_in[0];   // [N, 64]
    const float* W  = (const float*)d_in[1];   // [64, 64]
    const float* b  = (const float*)d_in[2];   // [64]
    const int*   ei = (const int*)d_in[3];     // [2, E]
    float* out = (float*)d_out;                // [N, 64]

    int E = in_sizes[3] / 2;
    const int* src = ei;
    const int* dst = ei + E;

    // 1) fused: gemm (unscaled) || adjacency fill  (R14 configuration)
    int ntiles = (N_NODES + GROWS - 1) / GROWS;
    int octs = (E + 7) / 8;
    int fillBlocks = (octs + 255) / 256;
    k_fused<<<GBLOCKS + fillBlocks, 256>>>(x, W, src, dst, E, N_NODES, ntiles);

    // 2) h *= rsqrt(deg+1)
    k_scale<<<(N_NODES * 16 + 255) / 256, 256>>>(N_NODES);

    // 3) gather-aggregate + expmap0 + proj — 64-thread blocks (2 warps)
    int npairs = N_NODES / 2;
    k_agg<<<(npairs * 32 + 63) / 64, 64>>>(b, out, npairs);
}